// round 1
// baseline (speedup 1.0000x reference)
#include <cuda_runtime.h>
#include <math.h>

// ---------------- problem constants ----------------
#define BB   4
#define NN   1024
#define KNB  32
#define CS   384
#define CZ   128
#define CH   16
#define HH   12
#define PQn  4
#define PVn  8
#define NODES (BB*NN)        // 4096
#define PROJ  1152           // q(192)+k(192)+v(192)+qpts(144)+kvpts(432)
#define EDGES (NODES*KNB)    // 131072
#define EOC   44             // b_bias(12) + pair(32)
#define CVC   960            // o(192)+o_pt(288)+dists(96)+o_pair(384)
#define COUT  384

// ---------------- scratch (device globals; no allocation) ----------------
__device__ float g_sln [NODES*CS];
__device__ float g_wcat[CS*PROJ];
__device__ float g_proj[NODES*PROJ];
__device__ float g_stat[EDGES*2];
__device__ float g_wz  [CZ*EOC];
__device__ float g_eo  [EDGES*EOC];
__device__ float g_cvec[NODES*CVC];

// ---------------- weight packing ----------------
__global__ void pack_wcat(const float* __restrict__ wq, const float* __restrict__ wk,
                          const float* __restrict__ wv, const float* __restrict__ wqp,
                          const float* __restrict__ wkv) {
    int idx = blockIdx.x * 256 + threadIdx.x;
    if (idx >= CS * PROJ) return;
    int i = idx / PROJ, j = idx % PROJ;
    float v;
    if      (j < 192) v = wq [i*192 + j];
    else if (j < 384) v = wk [i*192 + j - 192];
    else if (j < 576) v = wv [i*192 + j - 384];
    else if (j < 720) v = wqp[i*144 + j - 576];
    else              v = wkv[i*432 + j - 720];
    g_wcat[idx] = v;
}

__global__ void pack_wz(const float* __restrict__ wb, const float* __restrict__ wdz) {
    int idx = blockIdx.x * 256 + threadIdx.x;
    if (idx >= CZ * EOC) return;
    int i = idx / EOC, j = idx % EOC;
    g_wz[idx] = (j < 12) ? wb[i*12 + j] : wdz[i*32 + j - 12];
}

// ---------------- s layernorm (one block per node) ----------------
__global__ __launch_bounds__(128) void k_ln_s(const float* __restrict__ s,
                                              const float* __restrict__ gam,
                                              const float* __restrict__ bet) {
    int node = blockIdx.x;
    int tid  = threadIdx.x;
    const float* x = s + (size_t)node * CS;
    float v0 = x[tid], v1 = x[tid + 128], v2 = x[tid + 256];
    float sum = v0 + v1 + v2;
    float ssq = v0*v0 + v1*v1 + v2*v2;
    #pragma unroll
    for (int o = 16; o; o >>= 1) {
        sum += __shfl_xor_sync(0xffffffffu, sum, o);
        ssq += __shfl_xor_sync(0xffffffffu, ssq, o);
    }
    __shared__ float sa[4], sb[4];
    int w = tid >> 5, l = tid & 31;
    if (l == 0) { sa[w] = sum; sb[w] = ssq; }
    __syncthreads();
    sum = sa[0] + sa[1] + sa[2] + sa[3];
    ssq = sb[0] + sb[1] + sb[2] + sb[3];
    float mean = sum * (1.0f / CS);
    float var  = ssq * (1.0f / CS) - mean * mean;
    float rstd = rsqrtf(var + 1e-5f);
    float* o = g_sln + (size_t)node * CS;
    o[tid      ] = (v0 - mean) * rstd * gam[tid      ] + bet[tid      ];
    o[tid + 128] = (v1 - mean) * rstd * gam[tid + 128] + bet[tid + 128];
    o[tid + 256] = (v2 - mean) * rstd * gam[tid + 256] + bet[tid + 256];
}

// ---------------- z row stats (warp per edge row of 128) ----------------
__global__ __launch_bounds__(256) void k_zstats(const float* __restrict__ z) {
    int row  = blockIdx.x * 8 + (threadIdx.x >> 5);
    int lane = threadIdx.x & 31;
    float4 v = *(const float4*)(z + (size_t)row * CZ + lane * 4);
    float s  = v.x + v.y + v.z + v.w;
    float ss = v.x*v.x + v.y*v.y + v.z*v.z + v.w*v.w;
    #pragma unroll
    for (int o = 16; o; o >>= 1) {
        s  += __shfl_xor_sync(0xffffffffu, s,  o);
        ss += __shfl_xor_sync(0xffffffffu, ss, o);
    }
    if (lane == 0) {
        float mean = s * (1.0f / CZ);
        float var  = ss * (1.0f / CZ) - mean * mean;
        g_stat[row*2    ] = mean;
        g_stat[row*2 + 1] = rsqrtf(var + 1e-5f);
    }
}

// ---------------- z GEMM with LN fused into A-load: (131072x128)@(128x44) ----------------
// block: 128 rows x 44 cols, 256 threads, 2 rows x 11 cols per thread
extern __shared__ float zsm[];
__global__ __launch_bounds__(256) void k_zgemm(const float* __restrict__ z,
                                               const float* __restrict__ zsc,
                                               const float* __restrict__ zbi) {
    float* As = zsm;                 // [128][129]
    float* Ws = zsm + 128 * 129;     // [128][44]
    int tid = threadIdx.x;
    int r0  = blockIdx.x * 128;

    for (int i = tid; i < CZ * EOC; i += 256) Ws[i] = g_wz[i];
    #pragma unroll
    for (int t = 0; t < 16; t++) {
        int flat = (tid + t * 256) * 4;        // 0..65532
        int row  = flat >> 7;
        int col  = flat & 127;
        float mean = g_stat[(size_t)(r0 + row) * 2];
        float rstd = g_stat[(size_t)(r0 + row) * 2 + 1];
        float4 v = *(const float4*)(z + (size_t)(r0 + row) * CZ + col);
        As[row*129 + col + 0] = (v.x - mean) * rstd * zsc[col + 0] + zbi[col + 0];
        As[row*129 + col + 1] = (v.y - mean) * rstd * zsc[col + 1] + zbi[col + 1];
        As[row*129 + col + 2] = (v.z - mean) * rstd * zsc[col + 2] + zbi[col + 2];
        As[row*129 + col + 3] = (v.w - mean) * rstd * zsc[col + 3] + zbi[col + 3];
    }
    __syncthreads();

    int rA = tid >> 2;            // 0..63
    int rB = rA + 64;
    int c0 = (tid & 3) * 11;      // 0,11,22,33
    float acc0[11], acc1[11];
    #pragma unroll
    for (int j = 0; j < 11; j++) { acc0[j] = 0.f; acc1[j] = 0.f; }
    #pragma unroll 8
    for (int kk = 0; kk < CZ; kk++) {
        float a0 = As[rA*129 + kk];
        float a1 = As[rB*129 + kk];
        #pragma unroll
        for (int j = 0; j < 11; j++) {
            float w = Ws[kk*EOC + c0 + j];
            acc0[j] += a0 * w;
            acc1[j] += a1 * w;
        }
    }
    #pragma unroll
    for (int j = 0; j < 11; j++) {
        g_eo[(size_t)(r0 + rA) * EOC + c0 + j] = acc0[j];
        g_eo[(size_t)(r0 + rB) * EOC + c0 + j] = acc1[j];
    }
}

// ---------------- generic SGEMM: C[MxN] = A[MxK] @ B[KxN], 128x64 tile ----------------
#define BM 128
#define BN 64
#define BK 16
__global__ __launch_bounds__(256) void sgemm(const float* __restrict__ A,
                                             const float* __restrict__ B,
                                             float* __restrict__ C,
                                             int Kd, int Nd) {
    __shared__ float As[BK][BM + 4];   // [kk][row]
    __shared__ float Bs[BK][BN];
    int tid = threadIdx.x;
    int tx  = tid & 15;    // N dir (x4)
    int ty  = tid >> 4;    // M dir (x8)
    int m0  = blockIdx.x * BM;
    int n0  = blockIdx.y * BN;

    float acc[8][4];
    #pragma unroll
    for (int i = 0; i < 8; i++)
        #pragma unroll
        for (int j = 0; j < 4; j++) acc[i][j] = 0.f;

    for (int k0 = 0; k0 < Kd; k0 += BK) {
        #pragma unroll
        for (int t = 0; t < 2; t++) {
            int flat = (tid + t * 256) * 4;
            int row  = flat >> 4;
            int col  = flat & 15;
            float4 v = *(const float4*)(A + (size_t)(m0 + row) * Kd + k0 + col);
            As[col + 0][row] = v.x;
            As[col + 1][row] = v.y;
            As[col + 2][row] = v.z;
            As[col + 3][row] = v.w;
        }
        {
            int flat = tid * 4;
            int row  = flat >> 6;
            int col  = flat & 63;
            *(float4*)&Bs[row][col] =
                *(const float4*)(B + (size_t)(k0 + row) * Nd + n0 + col);
        }
        __syncthreads();
        #pragma unroll
        for (int kk = 0; kk < BK; kk++) {
            float4 b4  = *(float4*)&Bs[kk][tx * 4];
            float4 a40 = *(float4*)&As[kk][ty * 8];
            float4 a41 = *(float4*)&As[kk][ty * 8 + 4];
            float a[8] = {a40.x, a40.y, a40.z, a40.w, a41.x, a41.y, a41.z, a41.w};
            #pragma unroll
            for (int i = 0; i < 8; i++) {
                acc[i][0] += a[i] * b4.x;
                acc[i][1] += a[i] * b4.y;
                acc[i][2] += a[i] * b4.z;
                acc[i][3] += a[i] * b4.w;
            }
        }
        __syncthreads();
    }
    #pragma unroll
    for (int i = 0; i < 8; i++) {
        float4 o = {acc[i][0], acc[i][1], acc[i][2], acc[i][3]};
        *(float4*)(C + (size_t)(m0 + ty * 8 + i) * Nd + n0 + tx * 4) = o;
    }
}

// ---------------- attention: one block (128 thr) per node ----------------
// rot/trans cancel algebraically (orthonormal rot, softmax sums to 1):
//   |q_pts-k_pts|^2 == |q_raw-k_raw|^2 ;  o_pt == sum_k a * v_raw
__global__ __launch_bounds__(128) void k_attn(const int*   __restrict__ edge_index,
                                              const float* __restrict__ s_mask,
                                              const float* __restrict__ head_w) {
    int node = blockIdx.x;
    int tid  = threadIdx.x;
    int b    = node >> 10;

    __shared__ int   nbroff_sh[KNB];      // neighbor row * PROJ
    __shared__ float msk_sh[KNB];
    __shared__ float q_sh[HH * CH];
    __shared__ float qp_sh[HH * PQn * 3];
    __shared__ float a_sh[HH][KNB];
    __shared__ float opt_sh[HH * PVn * 3];
    __shared__ float hw_sh[HH];

    if (tid < KNB) {
        int idx = edge_index[(size_t)node * KNB + tid];
        nbroff_sh[tid] = (b * NN + idx) * PROJ;
        msk_sh[tid]    = s_mask[node] * s_mask[b * NN + idx];
    }
    for (int i = tid; i < HH * CH; i += 128)
        q_sh[i] = g_proj[(size_t)node * PROJ + i];
    for (int i = tid; i < HH * PQn * 3; i += 128)
        qp_sh[i] = g_proj[(size_t)node * PROJ + 576 + i];
    if (tid < HH)
        hw_sh[tid] = log1pf(__expf(head_w[tid])) * 0.13608276348795434f; // * rsqrt(54)
    __syncthreads();

    int lane = tid & 31, warp = tid >> 5;
    int no   = nbroff_sh[lane];
    float mk = msk_sh[lane];
    const float* kr = g_proj + no;

    #pragma unroll
    for (int hi = 0; hi < 3; hi++) {
        int h = warp * 3 + hi;
        const float4* q4 = (const float4*)(q_sh + h * CH);
        const float4* k4 = (const float4*)(kr + 192 + h * CH);
        float dot = 0.f;
        #pragma unroll
        for (int c = 0; c < 4; c++) {
            float4 qa = q4[c], kb = k4[c];
            dot += qa.x*kb.x + qa.y*kb.y + qa.z*kb.z + qa.w*kb.w;
        }
        float sq = 0.f;
        const float* qp = qp_sh + h * 12;
        const float* kp = kr + 720 + h * 36;
        #pragma unroll
        for (int j = 0; j < 12; j++) {
            float d = qp[j] - kp[j];
            sq += d * d;
        }
        float bias  = g_eo[(size_t)(node * KNB + lane) * EOC + h];
        float logit = dot * 0.14433756729740643f      // rsqrt(48)
                    + bias * 0.5773502691896258f      // rsqrt(3)
                    - 0.5f * hw_sh[h] * sq
                    + 100000.0f * (mk - 1.0f);
        float mx = logit;
        #pragma unroll
        for (int o = 16; o; o >>= 1) mx = fmaxf(mx, __shfl_xor_sync(0xffffffffu, mx, o));
        float e = __expf(logit - mx);
        float sm = e;
        #pragma unroll
        for (int o = 16; o; o >>= 1) sm += __shfl_xor_sync(0xffffffffu, sm, o);
        a_sh[h][lane] = e / sm;
    }
    __syncthreads();

    float* cv = g_cvec + (size_t)node * CVC;
    for (int oi = tid; oi < CVC; oi += 128) {
        float acc = 0.f;
        if (oi < 192) {                                   // o: h*16+c
            int h = oi >> 4;
            int off = 384 + oi;                           // v region
            #pragma unroll 8
            for (int k = 0; k < KNB; k++)
                acc += a_sh[h][k] * g_proj[nbroff_sh[k] + off];
            cv[oi] = acc;
        } else if (oi < 480) {                            // o_pt: h*24 + v*3 + d
            int j = oi - 192;
            int h = j / 24, r = j % 24;
            int off = 720 + h * 36 + 12 + r;              // v_pts region
            #pragma unroll 8
            for (int k = 0; k < KNB; k++)
                acc += a_sh[h][k] * g_proj[nbroff_sh[k] + off];
            opt_sh[j] = acc;
            cv[oi] = acc;
        } else if (oi >= 576) {                           // o_pair: h*32+c
            int j = oi - 576;
            int h = j >> 5, c = j & 31;
            const float* eb = g_eo + (size_t)(node * KNB) * EOC + 12 + c;
            #pragma unroll 8
            for (int k = 0; k < KNB; k++)
                acc += a_sh[h][k] * eb[(size_t)k * EOC];
            cv[oi] = acc;
        }
        // dists region [480,576) handled after sync
    }
    __syncthreads();
    if (tid < HH * PVn) {
        float x = opt_sh[tid*3], y = opt_sh[tid*3+1], zz = opt_sh[tid*3+2];
        cv[480 + tid] = sqrtf(x*x + y*y + zz*zz + 1e-8f);
    }
}

// ---------------- launch ----------------
extern "C" void kernel_launch(void* const* d_in, const int* in_sizes, int n_in,
                              void* d_out, int out_size) {
    const float* s           = (const float*)d_in[0];
    const float* z           = (const float*)d_in[1];
    const int*   edge_index  = (const int*)  d_in[2];
    // d_in[3] rot, d_in[4] trans: algebraically cancel -> unused
    const float* s_mask      = (const float*)d_in[5];
    const float* ln_s_scale  = (const float*)d_in[6];
    const float* ln_s_bias   = (const float*)d_in[7];
    const float* ln_z_scale  = (const float*)d_in[8];
    const float* ln_z_bias   = (const float*)d_in[9];
    const float* w_q         = (const float*)d_in[10];
    const float* w_k         = (const float*)d_in[11];
    const float* w_v         = (const float*)d_in[12];
    const float* w_q_pts     = (const float*)d_in[13];
    const float* w_kv_pts    = (const float*)d_in[14];
    const float* w_b         = (const float*)d_in[15];
    const float* w_down_z    = (const float*)d_in[16];
    const float* head_weights= (const float*)d_in[17];
    const float* w_out       = (const float*)d_in[18];
    float* out = (float*)d_out;

    static bool attr_set = false;
    // Setting the attribute is idempotent and cheap; do it unconditionally to
    // stay deterministic (no work-skipping involved).
    (void)attr_set;
    cudaFuncSetAttribute(k_zgemm, cudaFuncAttributeMaxDynamicSharedMemorySize, 92160);

    void *p_sln, *p_wcat, *p_proj, *p_cvec;
    cudaGetSymbolAddress(&p_sln,  g_sln);
    cudaGetSymbolAddress(&p_wcat, g_wcat);
    cudaGetSymbolAddress(&p_proj, g_proj);
    cudaGetSymbolAddress(&p_cvec, g_cvec);

    pack_wcat<<<(CS * PROJ + 255) / 256, 256>>>(w_q, w_k, w_v, w_q_pts, w_kv_pts);
    pack_wz  <<<(CZ * EOC  + 255) / 256, 256>>>(w_b, w_down_z);
    k_ln_s   <<<NODES, 128>>>(s, ln_s_scale, ln_s_bias);
    sgemm    <<<dim3(NODES / BM, PROJ / BN), 256>>>((const float*)p_sln,
                                                    (const float*)p_wcat,
                                                    (float*)p_proj, CS, PROJ);
    k_zstats <<<EDGES / 8, 256>>>(z);
    k_zgemm  <<<EDGES / 128, 256, (128 * 129 + CZ * EOC) * sizeof(float)>>>(z, ln_z_scale, ln_z_bias);
    k_attn   <<<NODES, 128>>>(edge_index, s_mask, head_weights);
    sgemm    <<<dim3(NODES / BM, COUT / BN), 256>>>((const float*)p_cvec,
                                                    w_out,
                                                    out, CVC, COUT);
}